// round 4
// baseline (speedup 1.0000x reference)
#include <cuda_runtime.h>
#include <math.h>

// ---------------------------------------------------------------------------
// IIDSegmentationLoss on GB300 — Round 4: x-paired FFMA2 + LDS.64 + prefetch
//
// Stage 1: p[dy,dx,i,j] = sum_{n,y,x} A[n,i,y+dy-7,x+dx-7] * B[n,j,y,x]
// Stage 2: scalar IID loss from the 225x10x10 joint histogram.
// ---------------------------------------------------------------------------

#define Tn      15            // shifts per axis
#define Kc      10            // channels
#define Hh      224
#define Ww      224
#define YT      8             // B rows per block
#define AROWS   (YT + 14)     // A rows incl. halo = 22
#define APITCH  240           // padded A row (x in [-7, 233)), even
#define IC      5             // i-channels per block (2 blocks cover k=10)
#define NBINS   (Tn*Tn*Kc*Kc) // 22500
#define NTASKS  (Tn*IC*2)     // 150 warp tasks per block: (dy, i, jgroup)
#define NCHUNK  (YT*Ww/64)    // 28 chunks of 64 px per task

typedef unsigned long long ull;

__device__ float g_p[NBINS];

// ---- packed f32x2 helpers (sm_100+) ----
#define FMA_F32X2(d, a, b, c) \
    asm("fma.rn.f32x2 %0, %1, %2, %3;" : "=l"(d) : "l"(a), "l"(b), "l"(c))
#define PACK_F32X2(out, lo, hi) \
    asm("mov.b64 %0, {%1, %2};" : "=l"(out) : "f"(lo), "f"(hi))
#define UNPACK_F32X2(lo, hi, in) \
    asm("mov.b64 {%0, %1}, %2;" : "=f"(lo), "=f"(hi) : "l"(in))

// ---------------------------------------------------------------------------
__global__ void zero_p_kernel() {
    int t = blockIdx.x * blockDim.x + threadIdx.x;
    if (t < NBINS) g_p[t] = 0.0f;
}

// ---------------------------------------------------------------------------
// Load one chunk's operands: lane owns pixel pair (x, x+1), g = c*64 + 2*lane.
// ---------------------------------------------------------------------------
struct ChunkBuf { ull w2[8]; ull bb[5]; };

__device__ __forceinline__ void load_chunk(
    const float* __restrict__ sAi,   // sA + (i*AROWS + dy)*APITCH
    const float* __restrict__ sBj,   // sB + jg*5*YT*Ww
    int c, int lane, ChunkBuf& buf)
{
    const int g   = c * 64 + 2 * lane;
    const int row = g / Ww;          // 0..7
    const int x   = g - row * Ww;    // even, <= 222
    const float* ar = sAi + row * APITCH + x;   // window A[x .. x+15]
    const float* br = sBj + row * Ww + x;
    #pragma unroll
    for (int q = 0; q < 8; ++q)
        buf.w2[q] = *(const ull*)(ar + 2 * q);
    #pragma unroll
    for (int jj = 0; jj < 5; ++jj)
        buf.bb[jj] = *(const ull*)(br + jj * (YT * Ww));
}

__device__ __forceinline__ void compute_chunk(const ChunkBuf& buf, ull acc[Tn][5])
{
    // name the 16 window floats
    float f[16];
    #pragma unroll
    for (int q = 0; q < 8; ++q)
        UNPACK_F32X2(f[2 * q], f[2 * q + 1], buf.w2[q]);
    // odd-shift pairs (A[x+2k+1], A[x+2k+2])
    ull od[7];
    #pragma unroll
    for (int k = 0; k < 7; ++k)
        PACK_F32X2(od[k], f[2 * k + 1], f[2 * k + 2]);

    #pragma unroll
    for (int jj = 0; jj < 5; ++jj) {
        const ull b = buf.bb[jj];
        #pragma unroll
        for (int d = 0; d < Tn; ++d) {
            const ull ap = (d & 1) ? od[d >> 1] : buf.w2[d >> 1];
            FMA_F32X2(acc[d][jj], ap, b, acc[d][jj]);
        }
    }
}

// ---------------------------------------------------------------------------
// grid: (28 y-groups, 16 n, 2 i-halves), 256 threads.
// smem: A strip [IC][AROWS][APITCH] (zero halo) + B strip [Kc][YT][Ww]
// ---------------------------------------------------------------------------
__global__ void __launch_bounds__(256, 1) corr_kernel(
    const float* __restrict__ A, const float* __restrict__ B)
{
    extern __shared__ float smem[];
    float* sA = smem;                         // IC*AROWS*APITCH = 26400 floats
    float* sB = smem + IC * AROWS * APITCH;   // Kc*YT*Ww        = 17920 floats

    const int yg = blockIdx.x;
    const int n  = blockIdx.y;
    const int ih = blockIdx.z;
    const int y0 = yg * YT;
    const int tid = threadIdx.x;

    // ---- stage A (with zero halo) ----
    const int atot = IC * AROWS * APITCH;
    for (int idx = tid; idx < atot; idx += 256) {
        int i    = idx / (AROWS * APITCH);
        int rest = idx % (AROWS * APITCH);
        int r    = rest / APITCH;
        int xx   = rest % APITCH;
        int gy   = y0 - 7 + r;
        int gx   = xx - 7;
        float v = 0.0f;
        if (gy >= 0 && gy < Hh && gx >= 0 && gx < Ww)
            v = A[(((size_t)n * Kc + ih * IC + i) * Hh + gy) * Ww + gx];
        sA[idx] = v;
    }
    // ---- stage B ----
    const int btot = Kc * YT * Ww;
    for (int idx = tid; idx < btot; idx += 256) {
        int j    = idx / (YT * Ww);
        int rest = idx % (YT * Ww);
        int yy   = rest / Ww;
        int x    = rest % Ww;
        sB[idx] = B[(((size_t)n * Kc + j) * Hh + (y0 + yy)) * Ww + x];
    }
    __syncthreads();

    const int w    = tid >> 5;
    const int lane = tid & 31;

    #pragma unroll 1
    for (int t = w; t < NTASKS; t += 8) {
        const int dy  = t / (IC * 2);
        const int rem = t % (IC * 2);
        const int i   = rem >> 1;
        const int jg  = rem & 1;

        const float* sAi = sA + (i * AROWS + dy) * APITCH;
        const float* sBj = sB + (jg * 5) * (YT * Ww);

        // acc[d][jj]: packed over (x even, x odd)
        ull acc[Tn][5];
        #pragma unroll
        for (int d = 0; d < Tn; ++d)
            #pragma unroll
            for (int jj = 0; jj < 5; ++jj) acc[d][jj] = 0ull;

        // ping-pong prefetch over 28 chunks
        ChunkBuf b0, b1;
        load_chunk(sAi, sBj, 0, lane, b0);
        #pragma unroll 1
        for (int c = 0; c < NCHUNK; c += 2) {
            load_chunk(sAi, sBj, c + 1, lane, b1);
            compute_chunk(b0, acc);
            if (c + 2 < NCHUNK) load_chunk(sAi, sBj, c + 2, lane, b0);
            compute_chunk(b1, acc);
        }

        // fold packed halves, then scalar butterfly over lanes
        float r[Tn][5];
        #pragma unroll
        for (int d = 0; d < Tn; ++d)
            #pragma unroll
            for (int jj = 0; jj < 5; ++jj) {
                float lo, hi;
                UNPACK_F32X2(lo, hi, acc[d][jj]);
                r[d][jj] = lo + hi;
            }
        #pragma unroll
        for (int off = 16; off >= 1; off >>= 1)
            #pragma unroll
            for (int d = 0; d < Tn; ++d)
                #pragma unroll
                for (int jj = 0; jj < 5; ++jj)
                    r[d][jj] += __shfl_xor_sync(0xffffffffu, r[d][jj], off);

        if (lane == 0) {
            const int ig = ih * IC + i;
            #pragma unroll
            for (int d = 0; d < Tn; ++d)
                #pragma unroll
                for (int jj = 0; jj < 5; ++jj)
                    atomicAdd(&g_p[((dy * Tn + d) * Kc + ig) * Kc + jg * 5 + jj],
                              r[d][jj]);
        }
    }
}

// ---------------------------------------------------------------------------
// Single-block loss kernel: exact transcription of the reference loss body.
// ---------------------------------------------------------------------------
__global__ void loss_kernel(float* __restrict__ out) {
    __shared__ float red[256];
    const int tid = threadIdx.x;

    // global min over p
    float m = 3.402823466e38f;
    for (int idx = tid; idx < NBINS; idx += 256) m = fminf(m, g_p[idx]);
    red[tid] = m;
    __syncthreads();
    for (int s = 128; s > 0; s >>= 1) {
        if (tid < s) red[tid] = fminf(red[tid], red[tid + s]);
        __syncthreads();
    }
    m = red[0];
    __syncthreads();

    float part = 0.0f;
    for (int t = tid; t < Tn * Tn; t += 256) {
        float v[Kc][Kc];
        float S = 0.0f;
        #pragma unroll
        for (int i = 0; i < Kc; ++i)
            #pragma unroll
            for (int j = 0; j < Kc; ++j) {
                float x = g_p[(t * Kc + i) * Kc + j] - m + 1e-16f;
                v[i][j] = x;
                S += x;
            }
        const float inv = 1.0f / S;

        // normalize + symmetrize in place
        #pragma unroll
        for (int i = 0; i < Kc; ++i) v[i][i] *= inv;
        #pragma unroll
        for (int i = 0; i < Kc; ++i)
            #pragma unroll
            for (int j = i + 1; j < Kc; ++j) {
                float s2 = 0.5f * (v[i][j] + v[j][i]) * inv;
                v[i][j] = s2;
                v[j][i] = s2;
            }

        float pi[Kc], pj[Kc];
        #pragma unroll
        for (int j = 0; j < Kc; ++j) pi[j] = 0.0f;
        #pragma unroll
        for (int i = 0; i < Kc; ++i) pj[i] = 0.0f;
        #pragma unroll
        for (int i = 0; i < Kc; ++i)
            #pragma unroll
            for (int j = 0; j < Kc; ++j) {
                pi[j] += v[i][j];
                pj[i] += v[i][j];
            }

        float l = 0.0f;
        #pragma unroll
        for (int i = 0; i < Kc; ++i)
            #pragma unroll
            for (int j = 0; j < Kc; ++j)
                l -= v[i][j] * (logf(v[i][j] + 1e-16f)
                                - logf(pi[j] + 1e-16f)
                                - logf(pj[i] + 1e-16f));
        part += l;
    }

    red[tid] = part;
    __syncthreads();
    for (int s = 128; s > 0; s >>= 1) {
        if (tid < s) red[tid] += red[tid + s];
        __syncthreads();
    }
    if (tid == 0) out[0] = red[0] / (float)(Tn * Tn);
}

// ---------------------------------------------------------------------------
extern "C" void kernel_launch(void* const* d_in, const int* in_sizes, int n_in,
                              void* d_out, int out_size)
{
    (void)in_sizes; (void)n_in; (void)out_size;
    const float* A = (const float*)d_in[0];   // x_out    (16,10,224,224) f32
    const float* B = (const float*)d_in[1];   // x_tf_out (16,10,224,224) f32
    float* out = (float*)d_out;

    const size_t smembytes = (size_t)(IC * AROWS * APITCH + Kc * YT * Ww) * sizeof(float);
    cudaFuncSetAttribute(corr_kernel,
                         cudaFuncAttributeMaxDynamicSharedMemorySize,
                         (int)smembytes);

    zero_p_kernel<<<(NBINS + 255) / 256, 256>>>();

    dim3 grid(Hh / YT, 16, 2);   // (28, 16, 2)
    corr_kernel<<<grid, 256, smembytes>>>(A, B);

    loss_kernel<<<1, 256>>>(out);
}

// round 8
// speedup vs baseline: 2.7029x; 2.7029x over previous
#include <cuda_runtime.h>
#include <math.h>
#include <stdint.h>

// ---------------------------------------------------------------------------
// IIDSegmentationLoss on GB300 — Round 8: cp.async + mma.sync.m16n8k8.tf32
// (all sm_80-baseline primitives; no TMA/mbarrier/ldmatrix)
//
// p[dy,dx,i,j] = sum_{n,y,x'} A[n,i,y+dy-7,x'] * B[n,j,y,x'+7-dx]
//   GEMM per K-block (n, y0, 64-wide x-chunk):
//     M = 80  : (i 0..4) * 16 + dy          (dy = row offset in A strip)
//     N = 152 : (dx 0..14) * 10 + j  (+pad) (dx = element offset in B strip)
//     K = 64  : x within chunk
// ---------------------------------------------------------------------------

#define Tn      15
#define Kc      10
#define Hh      224
#define Ww      224
#define NBINS   (Tn*Tn*Kc*Kc)        // 22500
#define NELEM   (16*Kc*Hh*Ww)        // 8,028,160
#define XCH     4
#define NBLK    (16*Hh*XCH)          // 14336 K-blocks per i-half
#define NCTA    74                   // grid.x (x2 i-halves = 148 CTAs)
#define APITCH  68                   // A words per row (64 + 4 pad) -> bank 4g+t
#define AWORDS  (80*APITCH)          // 5440
#define BPITCH  81                   // B words per row (78 + 3 pad)
#define BWORDS  (Kc*BPITCH)          // 810
#define SWORDS  6272                 // stage words (>= 5440+810), 128B multiple
#define SMEM_DYN (2*SWORDS*4)        // 50176 bytes
#define NMT     5                    // m16 tiles
#define NNT     19                   // n8 tiles (152 cols, 150 valid)

typedef uint32_t u32;

__device__ float g_p[NBINS];
__device__ u32 g_Atf[NELEM];   // tf32-rounded fp32 bits
__device__ u32 g_Btf[NELEM];

// ---------------- baseline PTX helpers ----------------
__device__ __forceinline__ u32 smem_u32(const void* p) {
    u32 a;
    asm("{ .reg .u64 t; cvta.to.shared.u64 t, %1; cvt.u32.u64 %0, t; }"
        : "=r"(a) : "l"(p));
    return a;
}

// 4B async copy with zero-fill when sz == 0 (src must still be a valid address)
#define CP_ASYNC4(dst, src, sz) \
    asm volatile("cp.async.ca.shared.global [%0], [%1], 4, %2;" \
                 :: "r"(dst), "l"(src), "r"(sz) : "memory")
#define CP_COMMIT() asm volatile("cp.async.commit_group;" ::: "memory")
#define CP_WAIT(N)  asm volatile("cp.async.wait_group %0;" :: "n"(N) : "memory")

#define MMA_TF32(d, a0, a1, a2, a3, b0, b1)                                    \
    asm volatile("mma.sync.aligned.m16n8k8.row.col.f32.tf32.tf32.f32 "        \
        "{%0,%1,%2,%3},{%4,%5,%6,%7},{%8,%9},{%0,%1,%2,%3};"                   \
        : "+f"((d)[0]), "+f"((d)[1]), "+f"((d)[2]), "+f"((d)[3])               \
        : "r"(a0), "r"(a1), "r"(a2), "r"(a3), "r"(b0), "r"(b1))

// ---------------------------------------------------------------------------
__global__ void zero_p_kernel() {
    int t = blockIdx.x * blockDim.x + threadIdx.x;
    if (t < NBINS) g_p[t] = 0.0f;
}

// fp32 -> tf32-rounded fp32 bits (unbiased round-to-nearest)
__global__ void convert_kernel(const float* __restrict__ A,
                               const float* __restrict__ B) {
    int i4 = (blockIdx.x * blockDim.x + threadIdx.x) * 4;
    if (i4 + 3 >= NELEM) return;
    float4 a = *(const float4*)(A + i4);
    float4 b = *(const float4*)(B + i4);
    u32 oa[4], ob[4];
    asm("cvt.rna.tf32.f32 %0, %1;" : "=r"(oa[0]) : "f"(a.x));
    asm("cvt.rna.tf32.f32 %0, %1;" : "=r"(oa[1]) : "f"(a.y));
    asm("cvt.rna.tf32.f32 %0, %1;" : "=r"(oa[2]) : "f"(a.z));
    asm("cvt.rna.tf32.f32 %0, %1;" : "=r"(oa[3]) : "f"(a.w));
    asm("cvt.rna.tf32.f32 %0, %1;" : "=r"(ob[0]) : "f"(b.x));
    asm("cvt.rna.tf32.f32 %0, %1;" : "=r"(ob[1]) : "f"(b.y));
    asm("cvt.rna.tf32.f32 %0, %1;" : "=r"(ob[2]) : "f"(b.z));
    asm("cvt.rna.tf32.f32 %0, %1;" : "=r"(ob[3]) : "f"(b.w));
    *(uint4*)(g_Atf + i4) = make_uint4(oa[0], oa[1], oa[2], oa[3]);
    *(uint4*)(g_Btf + i4) = make_uint4(ob[0], ob[1], ob[2], ob[3]);
}

// ---------------------------------------------------------------------------
// Stage one K-block into smem buffer s (all 256 threads cooperate).
// A strip: [5 ch][16 rows y0-7..y0+8][64 x], pitch 68 words.
// B strip: [10 ch][78 x = x0-7..x0+70],     pitch 81 words.
// ---------------------------------------------------------------------------
__device__ __forceinline__ void stage_load(u32 smbase, int s, int blk,
                                           int ih, int tid)
{
    const int n  = blk / (Hh * XCH);
    const int r  = blk - n * (Hh * XCH);
    const int y0 = r >> 2;
    const int x0 = (r & 3) << 6;
    const u32 st = smbase + (u32)s * (SWORDS * 4);

    // A: 5*16*64 = 5120 elems, 20 per thread
    #pragma unroll
    for (int q = 0; q < 20; ++q) {
        const int idx = tid + q * 256;
        const int i   = idx >> 10;
        const int rem = idx & 1023;
        const int rr  = rem >> 6;
        const int xx  = rem & 63;
        const int gy  = y0 - 7 + rr;
        const int gx  = x0 + xx;
        const u32 dst = st + (u32)((i * 16 + rr) * APITCH + xx) * 4u;
        const bool ok = (gy >= 0) && (gy < Hh) && (gx < Ww);
        const u32* src = ok
            ? g_Atf + ((size_t)((n * Kc) + ih * 5 + i) * Hh + gy) * Ww + gx
            : g_Atf;
        CP_ASYNC4(dst, src, ok ? 4u : 0u);
    }
    // B: 10*78 = 780 elems
    for (int idx = tid; idx < Kc * 78; idx += 256) {
        const int j  = idx / 78;
        const int xx = idx - j * 78;
        const int gx = x0 - 7 + xx;
        const u32 dst = st + (u32)(AWORDS + j * BPITCH + xx) * 4u;
        const bool ok = (gx >= 0) && (gx < Ww);
        const u32* src = ok
            ? g_Btf + ((size_t)(n * Kc + j) * Hh + y0) * Ww + gx
            : g_Btf;
        CP_ASYNC4(dst, src, ok ? 4u : 0u);
    }
}

// ---------------------------------------------------------------------------
// grid = (74, 2 i-halves), 256 threads, 8 warps all compute + stage.
// ---------------------------------------------------------------------------
__global__ void __launch_bounds__(256, 1) corr_kernel()
{
    extern __shared__ u32 sm[];
    const u32 smbase = smem_u32(sm);
    const int tid  = threadIdx.x;
    const int ih   = blockIdx.y;
    const int bx   = blockIdx.x;
    const int w    = tid >> 5;
    const int lane = tid & 31;
    const int g    = lane >> 2;      // groupID
    const int t    = lane & 3;       // threadID in group

    const int lo = (int)(((long long)bx * NBLK) / NCTA);
    const int hi = (int)(((long long)(bx + 1) * NBLK) / NCTA);

    // this warp's n8 tiles
    int ntv[3] = { w, w + 8, w + 16 };

    // A word offsets per m-tile (element (row, k): off + k)
    int aoff0[NMT], aoff1[NMT];
    #pragma unroll
    for (int m = 0; m < NMT; ++m) {
        aoff0[m] = (m * 16 + g) * APITCH;
        aoff1[m] = aoff0[m] + 8 * APITCH;
    }
    // B word offsets per n-tile (element (k, n): off + k)
    int boff[3];
    #pragma unroll
    for (int u = 0; u < 3; ++u) {
        int n = ntv[u] * 8 + g;
        if (n > 149) n = 149;                       // pad cols -> safe addr
        const int dxb = n / Kc, jb = n - dxb * Kc;
        boff[u] = AWORDS + jb * BPITCH + (14 - dxb);
    }

    float d[NMT][3][4];
    #pragma unroll
    for (int m = 0; m < NMT; ++m)
        #pragma unroll
        for (int u = 0; u < 3; ++u)
            #pragma unroll
            for (int e = 0; e < 4; ++e) d[m][u][e] = 0.0f;

    // ---- software pipeline: double-buffered cp.async ----
    stage_load(smbase, 0, lo, ih, tid);
    CP_COMMIT();

    for (int blk = lo; blk < hi; ++blk) {
        const int cur = (blk - lo) & 1;
        const bool more = (blk + 1 < hi);
        if (more) {
            stage_load(smbase, cur ^ 1, blk + 1, ih, tid);
            CP_COMMIT();
            CP_WAIT(1);
        } else {
            CP_WAIT(0);
        }
        __syncthreads();

        const u32* sc = sm + cur * SWORDS;
        #pragma unroll
        for (int kk = 0; kk < 64; kk += 8) {
            u32 bf[3][2];
            #pragma unroll
            for (int u = 0; u < 3; ++u) {
                bf[u][0] = sc[boff[u] + kk + t];
                bf[u][1] = sc[boff[u] + kk + t + 4];
            }
            #pragma unroll
            for (int m = 0; m < NMT; ++m) {
                const u32 a0 = sc[aoff0[m] + kk + t];
                const u32 a1 = sc[aoff1[m] + kk + t];
                const u32 a2 = sc[aoff0[m] + kk + t + 4];
                const u32 a3 = sc[aoff1[m] + kk + t + 4];
                #pragma unroll
                for (int u = 0; u < 3; ++u)
                    if (ntv[u] < NNT)
                        MMA_TF32(d[m][u], a0, a1, a2, a3, bf[u][0], bf[u][1]);
            }
        }
        __syncthreads();
    }

    // ---- epilogue: atomic fold into g_p ----
    #pragma unroll
    for (int m = 0; m < NMT; ++m) {
        const int ig = ih * 5 + m;
        #pragma unroll
        for (int u = 0; u < 3; ++u) {
            if (ntv[u] >= NNT) continue;
            #pragma unroll
            for (int e = 0; e < 4; ++e) {
                const int dy = g + (e >> 1) * 8;
                const int nn = ntv[u] * 8 + 2 * t + (e & 1);
                if (dy < Tn && nn < Tn * Kc) {
                    const int dx = nn / Kc;
                    const int j  = nn - dx * Kc;
                    atomicAdd(&g_p[((dy * Tn + dx) * Kc + ig) * Kc + j],
                              d[m][u][e]);
                }
            }
        }
    }
}

// ---------------------------------------------------------------------------
// Single-block loss kernel (unchanged, validated in R1-R4).
// ---------------------------------------------------------------------------
__global__ void loss_kernel(float* __restrict__ out) {
    __shared__ float red[256];
    const int tid = threadIdx.x;

    float m = 3.402823466e38f;
    for (int idx = tid; idx < NBINS; idx += 256) m = fminf(m, g_p[idx]);
    red[tid] = m;
    __syncthreads();
    for (int s = 128; s > 0; s >>= 1) {
        if (tid < s) red[tid] = fminf(red[tid], red[tid + s]);
        __syncthreads();
    }
    m = red[0];
    __syncthreads();

    float part = 0.0f;
    for (int t = tid; t < Tn * Tn; t += 256) {
        float v[Kc][Kc];
        float S = 0.0f;
        #pragma unroll
        for (int i = 0; i < Kc; ++i)
            #pragma unroll
            for (int j = 0; j < Kc; ++j) {
                float x = g_p[(t * Kc + i) * Kc + j] - m + 1e-16f;
                v[i][j] = x;
                S += x;
            }
        const float inv = 1.0f / S;
        #pragma unroll
        for (int i = 0; i < Kc; ++i) v[i][i] *= inv;
        #pragma unroll
        for (int i = 0; i < Kc; ++i)
            #pragma unroll
            for (int j = i + 1; j < Kc; ++j) {
                float s2 = 0.5f * (v[i][j] + v[j][i]) * inv;
                v[i][j] = s2;
                v[j][i] = s2;
            }
        float pi[Kc], pj[Kc];
        #pragma unroll
        for (int j = 0; j < Kc; ++j) pi[j] = 0.0f;
        #pragma unroll
        for (int i = 0; i < Kc; ++i) pj[i] = 0.0f;
        #pragma unroll
        for (int i = 0; i < Kc; ++i)
            #pragma unroll
            for (int j = 0; j < Kc; ++j) {
                pi[j] += v[i][j];
                pj[i] += v[i][j];
            }
        float l = 0.0f;
        #pragma unroll
        for (int i = 0; i < Kc; ++i)
            #pragma unroll
            for (int j = 0; j < Kc; ++j)
                l -= v[i][j] * (logf(v[i][j] + 1e-16f)
                                - logf(pi[j] + 1e-16f)
                                - logf(pj[i] + 1e-16f));
        part += l;
    }

    red[tid] = part;
    __syncthreads();
    for (int s = 128; s > 0; s >>= 1) {
        if (tid < s) red[tid] += red[tid + s];
        __syncthreads();
    }
    if (tid == 0) out[0] = red[0] / (float)(Tn * Tn);
}

// ---------------------------------------------------------------------------
extern "C" void kernel_launch(void* const* d_in, const int* in_sizes, int n_in,
                              void* d_out, int out_size)
{
    (void)in_sizes; (void)n_in; (void)out_size;
    const float* A = (const float*)d_in[0];   // x_out    (16,10,224,224) f32
    const float* B = (const float*)d_in[1];   // x_tf_out (16,10,224,224) f32
    float* out = (float*)d_out;

    cudaFuncSetAttribute(corr_kernel,
                         cudaFuncAttributeMaxDynamicSharedMemorySize, SMEM_DYN);

    zero_p_kernel<<<(NBINS + 255) / 256, 256>>>();
    convert_kernel<<<NELEM / 4 / 256, 256>>>(A, B);
    corr_kernel<<<dim3(NCTA, 2), 256, SMEM_DYN>>>();
    loss_kernel<<<1, 256>>>(out);
}

// round 9
// speedup vs baseline: 3.0995x; 1.1467x over previous
#include <cuda_runtime.h>
#include <math.h>
#include <stdint.h>

// ---------------------------------------------------------------------------
// IIDSegmentationLoss on GB300 — Round 9: 16B cp.async + M-split warps
//
// p[dy,dx,i,j] = sum_{n,y,x'} A[n,i,y+dy-7,x'] * B[n,j,y,x'+7-dx]
//   GEMM per K-block (n, y0, 64-wide x-chunk):
//     M = 80  : (i 0..4) * 16 + dy          (dy = row offset in A strip)
//     N = 152 : (dx 0..14) * 10 + j  (+pad) (dx = element offset in B strip)
//     K = 64  : x within chunk
//   Warps 0-3: m-tiles {0,1,2} x 5 n-tiles; warps 4-7: m-tiles {3,4} x 5.
// ---------------------------------------------------------------------------

#define Tn      15
#define Kc      10
#define Hh      224
#define Ww      224
#define NBINS   (Tn*Tn*Kc*Kc)        // 22500
#define NELEM   (16*Kc*Hh*Ww)        // 8,028,160
#define XCH     4
#define NBLK    (16*Hh*XCH)          // 14336 K-blocks per i-half
#define NCTA    74                   // grid.x (x2 i-halves = 148 CTAs)
#define APITCH  68                   // A words per row (64 + 4 pad)
#define AWORDS  (80*APITCH)          // 5440
#define BPITCH  81                   // B words per row (78 + 3 pad)
#define SWORDS  6272                 // stage words, 128B multiple
#define SMEM_DYN (2*SWORDS*4)        // 50176 bytes
#define NNT     19                   // valid n8 tiles (152 cols, 150 valid)

typedef uint32_t u32;

__device__ float g_p[NBINS];
__device__ float g_min;
__device__ u32 g_Atf[NELEM];   // tf32-rounded fp32 bits
__device__ u32 g_Btf[NELEM];

// ---------------- baseline PTX helpers ----------------
__device__ __forceinline__ u32 smem_u32(const void* p) {
    u32 a;
    asm("{ .reg .u64 t; cvta.to.shared.u64 t, %1; cvt.u32.u64 %0, t; }"
        : "=r"(a) : "l"(p));
    return a;
}

#define CP_ASYNC4(dst, src, sz) \
    asm volatile("cp.async.ca.shared.global [%0], [%1], 4, %2;" \
                 :: "r"(dst), "l"(src), "r"(sz) : "memory")
#define CP_ASYNC16(dst, src, sz) \
    asm volatile("cp.async.cg.shared.global [%0], [%1], 16, %2;" \
                 :: "r"(dst), "l"(src), "r"(sz) : "memory")
#define CP_COMMIT() asm volatile("cp.async.commit_group;" ::: "memory")
#define CP_WAIT(N)  asm volatile("cp.async.wait_group %0;" :: "n"(N) : "memory")

#define MMA_TF32(d, a0, a1, a2, a3, b0, b1)                                    \
    asm volatile("mma.sync.aligned.m16n8k8.row.col.f32.tf32.tf32.f32 "        \
        "{%0,%1,%2,%3},{%4,%5,%6,%7},{%8,%9},{%0,%1,%2,%3};"                   \
        : "+f"((d)[0]), "+f"((d)[1]), "+f"((d)[2]), "+f"((d)[3])               \
        : "r"(a0), "r"(a1), "r"(a2), "r"(a3), "r"(b0), "r"(b1))

// ---------------------------------------------------------------------------
__global__ void zero_p_kernel(float* __restrict__ out) {
    int t = blockIdx.x * blockDim.x + threadIdx.x;
    if (t < NBINS) g_p[t] = 0.0f;
    if (t == 0) out[0] = 0.0f;
}

// fp32 -> tf32-rounded fp32 bits (unbiased round-to-nearest)
__global__ void convert_kernel(const float* __restrict__ A,
                               const float* __restrict__ B) {
    int i4 = (blockIdx.x * blockDim.x + threadIdx.x) * 4;
    if (i4 + 3 >= NELEM) return;
    float4 a = *(const float4*)(A + i4);
    float4 b = *(const float4*)(B + i4);
    u32 oa[4], ob[4];
    asm("cvt.rna.tf32.f32 %0, %1;" : "=r"(oa[0]) : "f"(a.x));
    asm("cvt.rna.tf32.f32 %0, %1;" : "=r"(oa[1]) : "f"(a.y));
    asm("cvt.rna.tf32.f32 %0, %1;" : "=r"(oa[2]) : "f"(a.z));
    asm("cvt.rna.tf32.f32 %0, %1;" : "=r"(oa[3]) : "f"(a.w));
    asm("cvt.rna.tf32.f32 %0, %1;" : "=r"(ob[0]) : "f"(b.x));
    asm("cvt.rna.tf32.f32 %0, %1;" : "=r"(ob[1]) : "f"(b.y));
    asm("cvt.rna.tf32.f32 %0, %1;" : "=r"(ob[2]) : "f"(b.z));
    asm("cvt.rna.tf32.f32 %0, %1;" : "=r"(ob[3]) : "f"(b.w));
    *(uint4*)(g_Atf + i4) = make_uint4(oa[0], oa[1], oa[2], oa[3]);
    *(uint4*)(g_Btf + i4) = make_uint4(ob[0], ob[1], ob[2], ob[3]);
}

// ---------------------------------------------------------------------------
// Stage one K-block into smem buffer s.
// A: 16B cp.async (1280 ops); B: 4B cp.async (780 ops, unaligned window).
// ---------------------------------------------------------------------------
__device__ __forceinline__ void stage_load(u32 smbase, int s, int blk,
                                           int ih, int tid)
{
    const int n  = blk / (Hh * XCH);
    const int r  = blk - n * (Hh * XCH);
    const int y0 = r >> 2;
    const int x0 = (r & 3) << 6;
    const u32 st = smbase + (u32)s * (SWORDS * 4);

    // A: 5 ch x 16 rows x 16 four-word groups = 1280 16B ops, 5 per thread
    #pragma unroll
    for (int q = 0; q < 5; ++q) {
        const int idx = tid + q * 256;
        const int i   = idx >> 8;          // channel 0..4
        const int rem = idx & 255;
        const int rr  = rem >> 4;          // row 0..15
        const int xx  = (rem & 15) << 2;   // col group *4
        const int gy  = y0 - 7 + rr;
        const int gx  = x0 + xx;
        const u32 dst = st + (u32)((i * 16 + rr) * APITCH + xx) * 4u;
        const bool ok = (gy >= 0) && (gy < Hh) && (gx + 3 < Ww);
        const u32* src = ok
            ? g_Atf + ((size_t)((n * Kc) + ih * 5 + i) * Hh + gy) * Ww + gx
            : g_Atf;
        CP_ASYNC16(dst, src, ok ? 16u : 0u);
    }
    // B: 10 ch x 78 x-window (x0-7 .. x0+70), 4B granular
    for (int idx = tid; idx < Kc * 78; idx += 256) {
        const int j  = idx / 78;
        const int xx = idx - j * 78;
        const int gx = x0 - 7 + xx;
        const u32 dst = st + (u32)(AWORDS + j * BPITCH + xx) * 4u;
        const bool ok = (gx >= 0) && (gx < Ww);
        const u32* src = ok
            ? g_Btf + ((size_t)(n * Kc + j) * Hh + y0) * Ww + gx
            : g_Btf;
        CP_ASYNC4(dst, src, ok ? 4u : 0u);
    }
}

// ---------------------------------------------------------------------------
// grid = (74, 2 i-halves), 256 threads.
// ---------------------------------------------------------------------------
__global__ void __launch_bounds__(256, 1) corr_kernel()
{
    extern __shared__ u32 sm[];
    const u32 smbase = smem_u32(sm);
    const int tid  = threadIdx.x;
    const int ih   = blockIdx.y;
    const int bx   = blockIdx.x;
    const int w    = tid >> 5;
    const int lane = tid & 31;
    const int g    = lane >> 2;      // groupID
    const int t    = lane & 3;       // threadID in group

    const int lo = (int)(((long long)bx * NBLK) / NCTA);
    const int hi = (int)(((long long)(bx + 1) * NBLK) / NCTA);

    // warp layout: wg = m-group (0: m-tiles 0-2, 1: m-tiles 3-4), wn = n-quarter
    const int wg   = w >> 2;
    const int wn   = w & 3;
    const int mcnt = wg == 0 ? 3 : 2;

    int ntv[5];
    #pragma unroll
    for (int u = 0; u < 5; ++u) ntv[u] = wn * 5 + u;   // tile 19 invalid

    // A word offsets per m-tile
    int aoff0[3], aoff1[3];
    #pragma unroll
    for (int m = 0; m < 3; ++m) {
        const int mt = wg * 3 + m;            // 3,4 for wg=1 (m<2)
        aoff0[m] = (mt * 16 + g) * APITCH;
        aoff1[m] = aoff0[m] + 8 * APITCH;
    }
    // B word offsets per n-tile
    int boff[5];
    #pragma unroll
    for (int u = 0; u < 5; ++u) {
        int n = ntv[u] * 8 + g;
        if (n > 149) n = 149;                 // pad cols -> safe addr
        const int dxb = n / Kc, jb = n - dxb * Kc;
        boff[u] = AWORDS + jb * BPITCH + (14 - dxb);
    }

    float d[3][5][4];
    #pragma unroll
    for (int m = 0; m < 3; ++m)
        #pragma unroll
        for (int u = 0; u < 5; ++u)
            #pragma unroll
            for (int e = 0; e < 4; ++e) d[m][u][e] = 0.0f;

    // ---- software pipeline: double-buffered cp.async ----
    stage_load(smbase, 0, lo, ih, tid);
    CP_COMMIT();

    for (int blk = lo; blk < hi; ++blk) {
        const int cur = (blk - lo) & 1;
        const bool more = (blk + 1 < hi);
        if (more) {
            stage_load(smbase, cur ^ 1, blk + 1, ih, tid);
            CP_COMMIT();
            CP_WAIT(1);
        } else {
            CP_WAIT(0);
        }
        __syncthreads();

        const u32* sc = sm + cur * SWORDS;
        #pragma unroll
        for (int kk = 0; kk < 64; kk += 8) {
            u32 bf[5][2];
            #pragma unroll
            for (int u = 0; u < 5; ++u) {
                if (ntv[u] < NNT) {
                    bf[u][0] = sc[boff[u] + kk + t];
                    bf[u][1] = sc[boff[u] + kk + t + 4];
                }
            }
            #pragma unroll
            for (int m = 0; m < 3; ++m) {
                if (m < mcnt) {
                    const u32 a0 = sc[aoff0[m] + kk + t];
                    const u32 a1 = sc[aoff1[m] + kk + t];
                    const u32 a2 = sc[aoff0[m] + kk + t + 4];
                    const u32 a3 = sc[aoff1[m] + kk + t + 4];
                    #pragma unroll
                    for (int u = 0; u < 5; ++u)
                        if (ntv[u] < NNT)
                            MMA_TF32(d[m][u], a0, a1, a2, a3, bf[u][0], bf[u][1]);
                }
            }
        }
        __syncthreads();
    }

    // ---- epilogue: atomic fold into g_p ----
    #pragma unroll
    for (int m = 0; m < 3; ++m) {
        if (m >= mcnt) continue;
        const int ig = ih * 5 + wg * 3 + m;
        #pragma unroll
        for (int u = 0; u < 5; ++u) {
            if (ntv[u] >= NNT) continue;
            #pragma unroll
            for (int e = 0; e < 4; ++e) {
                const int dy = g + (e >> 1) * 8;
                const int nn = ntv[u] * 8 + 2 * t + (e & 1);
                if (dy < Tn && nn < Tn * Kc) {
                    const int dx = nn / Kc;
                    const int j  = nn - dx * Kc;
                    atomicAdd(&g_p[((dy * Tn + dx) * Kc + ig) * Kc + j],
                              d[m][u][e]);
                }
            }
        }
    }
}

// ---------------------------------------------------------------------------
// Loss stage, parallelized: min kernel (1 block) + per-shift loss (225 blocks).
// ---------------------------------------------------------------------------
__global__ void min_kernel() {
    __shared__ float red[256];
    const int tid = threadIdx.x;
    float m = 3.402823466e38f;
    for (int idx = tid; idx < NBINS; idx += 256) m = fminf(m, g_p[idx]);
    red[tid] = m;
    __syncthreads();
    for (int s = 128; s > 0; s >>= 1) {
        if (tid < s) red[tid] = fminf(red[tid], red[tid + s]);
        __syncthreads();
    }
    if (tid == 0) g_min = red[0];
}

__global__ void loss_kernel(float* __restrict__ out) {
    __shared__ float sv[100];    // shifted values
    __shared__ float ss[100];    // symmetrized/normalized
    __shared__ float red[128];
    const int t   = blockIdx.x;          // shift index 0..224
    const int tid = threadIdx.x;         // 0..127
    const float m = g_min;

    float v = 0.0f;
    if (tid < 100) {
        v = g_p[t * 100 + tid] - m + 1e-16f;
        sv[tid] = v;
    }
    red[tid] = (tid < 100) ? v : 0.0f;
    __syncthreads();
    for (int s = 64; s > 0; s >>= 1) {
        if (tid < s) red[tid] += red[tid + s];
        __syncthreads();
    }
    const float inv = 1.0f / red[0];
    __syncthreads();

    const int i = tid / 10, j = tid - (tid / 10) * 10;
    float sym = 0.0f;
    if (tid < 100) {
        sym = (i == j) ? v * inv : 0.5f * (v + sv[j * 10 + i]) * inv;
        ss[tid] = sym;
    }
    __syncthreads();

    float l = 0.0f;
    if (tid < 100) {
        float pi = 0.0f, pj = 0.0f;
        #pragma unroll
        for (int q = 0; q < 10; ++q) {
            pi += ss[q * 10 + j];    // sum over i -> marginal indexed by j
            pj += ss[i * 10 + q];    // sum over j -> marginal indexed by i
        }
        l = -sym * (logf(sym + 1e-16f) - logf(pi + 1e-16f) - logf(pj + 1e-16f));
    }
    red[tid] = l;
    __syncthreads();
    for (int s = 64; s > 0; s >>= 1) {
        if (tid < s) red[tid] += red[tid + s];
        __syncthreads();
    }
    if (tid == 0) atomicAdd(out, red[0] * (1.0f / (Tn * Tn)));
}

// ---------------------------------------------------------------------------
extern "C" void kernel_launch(void* const* d_in, const int* in_sizes, int n_in,
                              void* d_out, int out_size)
{
    (void)in_sizes; (void)n_in; (void)out_size;
    const float* A = (const float*)d_in[0];   // x_out    (16,10,224,224) f32
    const float* B = (const float*)d_in[1];   // x_tf_out (16,10,224,224) f32
    float* out = (float*)d_out;

    cudaFuncSetAttribute(corr_kernel,
                         cudaFuncAttributeMaxDynamicSharedMemorySize, SMEM_DYN);

    zero_p_kernel<<<(NBINS + 255) / 256, 256>>>(out);
    convert_kernel<<<NELEM / 4 / 256, 256>>>(A, B);
    corr_kernel<<<dim3(NCTA, 2), 256, SMEM_DYN>>>();
    min_kernel<<<1, 256>>>();
    loss_kernel<<<Tn * Tn, 128>>>(out);
}

// round 12
// speedup vs baseline: 7.9857x; 2.5764x over previous
#include <cuda_runtime.h>
#include <cuda_fp16.h>
#include <math.h>
#include <stdint.h>

// ---------------------------------------------------------------------------
// IIDSegmentationLoss on GB300 — Round 11: fp16 m16n8k16 (R10 + compile fix)
//
// p[dy,dx,i,j] = sum_{n,y,k} A[n,i,y+dy-7,x0+k] * B[n,j,y,x0+k+7-dx]
//   GEMM per K-block (n, y0, 112-wide x-chunk):
//     M = 80  : (i 0..4)*16 + dy      N = 152 : (dx)*10 + j (+2 pad)
//     K = 112 : 7 k-steps of 16
//   B stored twice in global (padded + one-element-shifted copy) so every
//   dx shift yields 4B-aligned fp16 pairs in smem.
// ---------------------------------------------------------------------------

#define Tn      15
#define Kc      10
#define Hh      224
#define Ww      224
#define NBINS   (Tn*Tn*Kc*Kc)        // 22500
#define NELEM   (16*Kc*Hh*Ww)        // 8,028,160
#define BPW     240                  // padded B row width (x = -8 .. 231)
#define NBELEM  (16*Kc*Hh*BPW)
#define XCH     2                    // x-chunks of 112 (exact)
#define KCH     112
#define NBLK    (16*Hh*XCH)          // 7168 K-blocks per i-half
#define NCTA    148                  // grid.x (x2 i-halves = 296 CTAs, 2/SM)
#define APITCHW 60                   // A row pitch in words (112 fp16 + pad)
#define AWORDS  (80*APITCHW)         // 4800
#define BPITCHW 68                   // B row pitch in words (64 + pad)
#define CB0     AWORDS               // copy0 base word
#define CB1     (AWORDS + Kc*BPITCHW)   // 5480
#define SWORDS  6176                 // stage words (5480+680=6160, pad)
#define SMEM_DYN (2*SWORDS*4)        // 49408 bytes
#define NNT     19                   // n8 tiles (152 cols, 150 valid)

typedef uint32_t u32;

__device__ float g_p[NBINS];
__device__ unsigned g_min_bits;
__device__ __half g_Ah[NELEM];       // fp16 A, plain [160][224][224]
__device__ __half g_Bp[NBELEM];      // fp16 B, padded [160][224][240], x at xp-8
__device__ __half g_Bp2[NBELEM];     // shifted copy: x at xp-7

// ---------------- baseline PTX helpers ----------------
__device__ __forceinline__ u32 smem_u32(const void* p) {
    u32 a;
    asm("{ .reg .u64 t; cvta.to.shared.u64 t, %1; cvt.u32.u64 %0, t; }"
        : "=r"(a) : "l"(p));
    return a;
}

__device__ __forceinline__ u32 h2_bits(__half2 h) {
    return *reinterpret_cast<u32*>(&h);
}

#define CP_ASYNC16(dst, src, sz) \
    asm volatile("cp.async.cg.shared.global [%0], [%1], 16, %2;" \
                 :: "r"(dst), "l"(src), "r"(sz) : "memory")
#define CP_COMMIT() asm volatile("cp.async.commit_group;" ::: "memory")
#define CP_WAIT(N)  asm volatile("cp.async.wait_group %0;" :: "n"(N) : "memory")

#define MMA_F16(d, a0, a1, a2, a3, b0, b1)                                     \
    asm volatile("mma.sync.aligned.m16n8k16.row.col.f32.f16.f16.f32 "         \
        "{%0,%1,%2,%3},{%4,%5,%6,%7},{%8,%9},{%0,%1,%2,%3};"                   \
        : "+f"((d)[0]), "+f"((d)[1]), "+f"((d)[2]), "+f"((d)[3])               \
        : "r"(a0), "r"(a1), "r"(a2), "r"(a3), "r"(b0), "r"(b1))

// ---------------------------------------------------------------------------
__global__ void zero_p_kernel(float* __restrict__ out) {
    int t = blockIdx.x * blockDim.x + threadIdx.x;
    if (t < NBINS) g_p[t] = 0.0f;
    if (t == 0) { out[0] = 0.0f; g_min_bits = 0x7f7fffffu; }
}

// fp32 -> fp16 into A (plain) and B (padded + shifted copies)
__global__ void convert_kernel(const float* __restrict__ A,
                               const float* __restrict__ B) {
    int i4 = (blockIdx.x * blockDim.x + threadIdx.x) * 4;
    if (i4 + 3 >= NELEM) return;
    float4 a = *(const float4*)(A + i4);
    float4 b = *(const float4*)(B + i4);
    __half2 a01 = __floats2half2_rn(a.x, a.y);
    __half2 a23 = __floats2half2_rn(a.z, a.w);
    __half2 b01 = __floats2half2_rn(b.x, b.y);
    __half2 b23 = __floats2half2_rn(b.z, b.w);
    // A: same linear layout
    *(uint2*)(g_Ah + i4) = make_uint2(h2_bits(a01), h2_bits(a23));
    // B: padded rows
    int ch = i4 / (Hh * Ww);
    int r  = i4 - ch * (Hh * Ww);
    int y  = r / Ww;
    int x  = r - y * Ww;                     // multiple of 4
    size_t rb = ((size_t)ch * Hh + y) * BPW;
    *(uint2*)(g_Bp + rb + x + 8) = make_uint2(h2_bits(b01), h2_bits(b23));
    // shifted copy: element at padded index xp holds B[x = xp - 7]
    // write pairs (b.x,b.y),(b.z,b.w) at xp = x+7 (odd) -> do aligned u32
    // stores of pairs (prev.w? no) — simplest correct: 4 scalar stores.
    __half* p2 = g_Bp2 + rb + x + 7;
    p2[0] = __low2half(b01);  p2[1] = __high2half(b01);
    p2[2] = __low2half(b23);  p2[3] = __high2half(b23);
}

// ---------------------------------------------------------------------------
// Stage one K-block (n, y0, x0) into smem buffer s. All 16B aligned cp.async.
// A strip: 5 ch x 16 rows x 112 fp16 (pitch 60 words).
// B: two parity copies, 10 ch x 128 fp16 window (xp = x0 .. x0+127).
// ---------------------------------------------------------------------------
__device__ __forceinline__ void stage_load(u32 smbase, int s, int blk,
                                           int ih, int tid)
{
    const int n  = blk / (Hh * XCH);
    const int r  = blk - n * (Hh * XCH);
    const int y0 = r >> 1;
    const int x0 = (r & 1) * KCH;
    const u32 st = smbase + (u32)s * (SWORDS * 4);

    // A: 5*16*14 = 1120 16B ops
    #pragma unroll
    for (int q = 0; q < 5; ++q) {
        const int idx = tid + q * 256;
        if (idx < 1120) {
            const int i   = idx / 224;
            const int rem = idx - i * 224;
            const int rr  = rem / 14;
            const int c   = rem - rr * 14;
            const int gy  = y0 - 7 + rr;
            const u32 dst = st + (u32)((i * 16 + rr) * APITCHW + c * 4) * 4u;
            const bool ok = (gy >= 0) && (gy < Hh);
            const __half* src = ok
                ? g_Ah + ((size_t)((n * Kc) + ih * 5 + i) * Hh + gy) * Ww + x0 + c * 8
                : g_Ah;
            CP_ASYNC16(dst, src, ok ? 16u : 0u);
        }
    }
    // B: 2 copies x 10 ch x 16 16B ops = 320 ops (padding pre-zeroed in global)
    {
        #pragma unroll
        for (int q = 0; q < 2; ++q) {
            const int id2 = tid + q * 256;
            if (id2 < 320) {
                const int cp = (id2 >> 4) >= Kc ? 1 : 0;
                const int jj = (id2 >> 4) - cp * Kc;
                const int c  = id2 & 15;
                const __half* gsrc = (cp ? g_Bp2 : g_Bp)
                    + ((size_t)(n * Kc + jj) * Hh + y0) * BPW + x0 + c * 8;
                const u32 dst = st
                    + (u32)((cp ? CB1 : CB0) + jj * BPITCHW + c * 4) * 4u;
                CP_ASYNC16(dst, gsrc, 16u);
            }
        }
    }
}

// ---------------------------------------------------------------------------
// grid = (148, 2 i-halves), 256 threads, 2 CTAs/SM.
// ---------------------------------------------------------------------------
__global__ void __launch_bounds__(256, 2) corr_kernel()
{
    extern __shared__ u32 sm[];
    const u32 smbase = smem_u32(sm);
    const int tid  = threadIdx.x;
    const int ih   = blockIdx.y;
    const int bx   = blockIdx.x;
    const int w    = tid >> 5;
    const int lane = tid & 31;
    const int g    = lane >> 2;
    const int t    = lane & 3;

    const int lo = (int)(((long long)bx * NBLK) / NCTA);
    const int hi = (int)(((long long)(bx + 1) * NBLK) / NCTA);

    const int wg   = w >> 2;          // m-group: 0 -> tiles 0-2, 1 -> 3-4
    const int wn   = w & 3;           // n-quarter
    const int mcnt = wg == 0 ? 3 : 2;

    int ntv[5];
    #pragma unroll
    for (int u = 0; u < 5; ++u) ntv[u] = wn * 5 + u;

    int aoff[3];
    #pragma unroll
    for (int m = 0; m < 3; ++m)
        aoff[m] = ((wg * 3 + m) * 16 + g) * APITCHW;

    int boff[5];
    #pragma unroll
    for (int u = 0; u < 5; ++u) {
        int n = ntv[u] * 8 + g;
        if (n > 149) n = 149;
        const int dxb = n / Kc, jb = n - dxb * Kc;
        const int s15 = 15 - dxb;                       // 1..15
        boff[u] = (s15 & 1)
            ? CB1 + jb * BPITCHW + ((s15 - 1) >> 1)     // odd  -> shifted copy
            : CB0 + jb * BPITCHW + (s15 >> 1);          // even -> aligned copy
    }

    float d[3][5][4];
    #pragma unroll
    for (int m = 0; m < 3; ++m)
        #pragma unroll
        for (int u = 0; u < 5; ++u)
            #pragma unroll
            for (int e = 0; e < 4; ++e) d[m][u][e] = 0.0f;

    stage_load(smbase, 0, lo, ih, tid);
    CP_COMMIT();

    for (int blk = lo; blk < hi; ++blk) {
        const int cur = (blk - lo) & 1;
        const bool more = (blk + 1 < hi);
        if (more) {
            stage_load(smbase, cur ^ 1, blk + 1, ih, tid);
            CP_COMMIT();
            CP_WAIT(1);
        } else {
            CP_WAIT(0);
        }
        __syncthreads();

        const u32* sc = sm + cur * SWORDS;
        #pragma unroll
        for (int ks = 0; ks < 7; ++ks) {
            const int kw = ks * 8;                       // k-step word offset
            u32 bf[5][2];
            #pragma unroll
            for (int u = 0; u < 5; ++u) {
                if (ntv[u] < NNT) {
                    bf[u][0] = sc[boff[u] + kw + t];
                    bf[u][1] = sc[boff[u] + kw + t + 4];
                }
            }
            #pragma unroll
            for (int m = 0; m < 3; ++m) {
                if (m < mcnt) {
                    const u32 a0 = sc[aoff[m] + kw + t];
                    const u32 a1 = sc[aoff[m] + 8 * APITCHW + kw + t];
                    const u32 a2 = sc[aoff[m] + kw + t + 4];
                    const u32 a3 = sc[aoff[m] + 8 * APITCHW + kw + t + 4];
                    #pragma unroll
                    for (int u = 0; u < 5; ++u)
                        if (ntv[u] < NNT)
                            MMA_F16(d[m][u], a0, a1, a2, a3, bf[u][0], bf[u][1]);
                }
            }
        }
        __syncthreads();
    }

    // ---- epilogue: atomic fold into g_p ----
    #pragma unroll
    for (int m = 0; m < 3; ++m) {
        if (m >= mcnt) continue;
        const int ig = ih * 5 + wg * 3 + m;
        #pragma unroll
        for (int u = 0; u < 5; ++u) {
            if (ntv[u] >= NNT) continue;
            #pragma unroll
            for (int e = 0; e < 4; ++e) {
                const int dy = g + (e >> 1) * 8;
                const int nn = ntv[u] * 8 + 2 * t + (e & 1);
                if (dy < Tn && nn < Tn * Kc) {
                    const int dx = nn / Kc;
                    const int j  = nn - dx * Kc;
                    atomicAdd(&g_p[((dy * Tn + dx) * Kc + ig) * Kc + j],
                              d[m][u][e]);
                }
            }
        }
    }
}

// ---------------------------------------------------------------------------
// min (parallel, atomicMin on positive-float bits) + per-shift loss.
// ---------------------------------------------------------------------------
__global__ void min_kernel() {
    __shared__ float red[256];
    const int tid = threadIdx.x;
    const int idx = blockIdx.x * 256 + tid;
    float m = (idx < NBINS) ? g_p[idx] : 3.402823466e38f;
    red[tid] = m;
    __syncthreads();
    for (int s = 128; s > 0; s >>= 1) {
        if (tid < s) red[tid] = fminf(red[tid], red[tid + s]);
        __syncthreads();
    }
    if (tid == 0) atomicMin(&g_min_bits, __float_as_uint(red[0]));
}

__global__ void loss_kernel(float* __restrict__ out) {
    __shared__ float sv[100];
    __shared__ float ss[100];
    __shared__ float red[128];
    const int t   = blockIdx.x;          // shift 0..224
    const int tid = threadIdx.x;         // 0..127
    const float m = __uint_as_float(g_min_bits);

    float v = 0.0f;
    if (tid < 100) {
        v = g_p[t * 100 + tid] - m + 1e-16f;
        sv[tid] = v;
    }
    red[tid] = (tid < 100) ? v : 0.0f;
    __syncthreads();
    for (int s = 64; s > 0; s >>= 1) {
        if (tid < s) red[tid] += red[tid + s];
        __syncthreads();
    }
    const float inv = 1.0f / red[0];
    __syncthreads();

    const int i = tid / 10, j = tid - (tid / 10) * 10;
    float sym = 0.0f;
    if (tid < 100) {
        sym = (i == j) ? v * inv : 0.5f * (v + sv[j * 10 + i]) * inv;
        ss[tid] = sym;
    }
    __syncthreads();

    float l = 0.0f;
    if (tid < 100) {
        float pi = 0.0f, pj = 0.0f;
        #pragma unroll
        for (int q = 0; q < 10; ++q) {
            pi += ss[q * 10 + j];
            pj += ss[i * 10 + q];
        }
        l = -sym * (logf(sym + 1e-16f) - logf(pi + 1e-16f) - logf(pj + 1e-16f));
    }
    red[tid] = l;
    __syncthreads();
    for (int s = 64; s > 0; s >>= 1) {
        if (tid < s) red[tid] += red[tid + s];
        __syncthreads();
    }
    if (tid == 0) atomicAdd(out, red[0] * (1.0f / (Tn * Tn)));
}

// ---------------------------------------------------------------------------
extern "C" void kernel_launch(void* const* d_in, const int* in_sizes, int n_in,
                              void* d_out, int out_size)
{
    (void)in_sizes; (void)n_in; (void)out_size;
    const float* A = (const float*)d_in[0];   // x_out    (16,10,224,224) f32
    const float* B = (const float*)d_in[1];   // x_tf_out (16,10,224,224) f32
    float* out = (float*)d_out;

    cudaFuncSetAttribute(corr_kernel,
                         cudaFuncAttributeMaxDynamicSharedMemorySize, SMEM_DYN);

    zero_p_kernel<<<(NBINS + 255) / 256, 256>>>(out);
    convert_kernel<<<NELEM / 4 / 256, 256>>>(A, B);
    corr_kernel<<<dim3(NCTA, 2), 256, SMEM_DYN>>>();
    min_kernel<<<(NBINS + 255) / 256, 256>>>();
    loss_kernel<<<Tn * Tn, 128>>>(out);
}

// round 15
// speedup vs baseline: 8.2008x; 1.0269x over previous
#include <cuda_runtime.h>
#include <cuda_fp16.h>
#include <math.h>
#include <stdint.h>

// ---------------------------------------------------------------------------
// IIDSegmentationLoss on GB300 — Round 13: 3-stage pipeline, 1 sync/iter
//
// p[dy,dx,i,j] = sum_{n,y,k} A[n,i,y+dy-7,x0+k] * B[n,j,y,x0+k+7-dx]
//   GEMM per K-block (n, y0, 112-wide x-chunk):
//     M = 80  : (i 0..4)*16 + dy      N = 152 : (dx)*10 + j (+2 pad)
//     K = 112 : 7 k-steps of 16
//   B stored twice in global (padded + one-element-shifted copy) so every
//   dx shift yields 4B-aligned fp16 pairs in smem.
// ---------------------------------------------------------------------------

#define Tn      15
#define Kc      10
#define Hh      224
#define Ww      224
#define NBINS   (Tn*Tn*Kc*Kc)        // 22500
#define NELEM   (16*Kc*Hh*Ww)        // 8,028,160
#define BPW     240                  // padded B row width (x = -8 .. 231)
#define NBELEM  (16*Kc*Hh*BPW)
#define XCH     2                    // x-chunks of 112 (exact)
#define KCH     112
#define NBLK    (16*Hh*XCH)          // 7168 K-blocks per i-half
#define NCTA    148                  // grid.x (x2 i-halves = 296 CTAs, 2/SM)
#define APITCHW 60                   // A row pitch in words (112 fp16 + pad)
#define AWORDS  (80*APITCHW)         // 4800
#define BPITCHW 68                   // B row pitch in words (64 + pad)
#define CB0     AWORDS               // copy0 base word
#define CB1     (AWORDS + Kc*BPITCHW)   // 5480
#define SWORDS  6176                 // stage words (5480+680=6160, pad)
#define NST     3                    // pipeline stages
#define SMEM_DYN (NST*SWORDS*4)      // 74112 bytes (x2 CTA = 148KB <= 228KB)
#define NNT     19                   // n8 tiles (152 cols, 150 valid)

typedef uint32_t u32;

__device__ float g_p[NBINS];
__device__ unsigned g_min_bits;
__device__ __half g_Ah[NELEM];       // fp16 A, plain [160][224][224]
__device__ __half g_Bp[NBELEM];      // fp16 B, padded [160][224][240], x at xp-8
__device__ __half g_Bp2[NBELEM];     // shifted copy: x at xp-7

// ---------------- baseline PTX helpers ----------------
__device__ __forceinline__ u32 smem_u32(const void* p) {
    u32 a;
    asm("{ .reg .u64 t; cvta.to.shared.u64 t, %1; cvt.u32.u64 %0, t; }"
        : "=r"(a) : "l"(p));
    return a;
}

__device__ __forceinline__ u32 h2_bits(__half2 h) {
    return *reinterpret_cast<u32*>(&h);
}

#define CP_ASYNC16(dst, src, sz) \
    asm volatile("cp.async.cg.shared.global [%0], [%1], 16, %2;" \
                 :: "r"(dst), "l"(src), "r"(sz) : "memory")
#define CP_COMMIT() asm volatile("cp.async.commit_group;" ::: "memory")
#define CP_WAIT(N)  asm volatile("cp.async.wait_group %0;" :: "n"(N) : "memory")

#define MMA_F16(d, a0, a1, a2, a3, b0, b1)                                     \
    asm volatile("mma.sync.aligned.m16n8k16.row.col.f32.f16.f16.f32 "         \
        "{%0,%1,%2,%3},{%4,%5,%6,%7},{%8,%9},{%0,%1,%2,%3};"                   \
        : "+f"((d)[0]), "+f"((d)[1]), "+f"((d)[2]), "+f"((d)[3])               \
        : "r"(a0), "r"(a1), "r"(a2), "r"(a3), "r"(b0), "r"(b1))

// ---------------------------------------------------------------------------
// fp32 -> fp16 into A (plain) and B (padded + shifted copies); also zeros g_p.
__global__ void convert_kernel(const float* __restrict__ A,
                               const float* __restrict__ B,
                               float* __restrict__ out) {
    const int gt = blockIdx.x * blockDim.x + threadIdx.x;
    if (gt < NBINS) g_p[gt] = 0.0f;
    if (gt == 0) { out[0] = 0.0f; g_min_bits = 0x7f7fffffu; }

    int i4 = gt * 4;
    if (i4 + 3 >= NELEM) return;
    float4 a = *(const float4*)(A + i4);
    float4 b = *(const float4*)(B + i4);
    __half2 a01 = __floats2half2_rn(a.x, a.y);
    __half2 a23 = __floats2half2_rn(a.z, a.w);
    __half2 b01 = __floats2half2_rn(b.x, b.y);
    __half2 b23 = __floats2half2_rn(b.z, b.w);
    *(uint2*)(g_Ah + i4) = make_uint2(h2_bits(a01), h2_bits(a23));
    int ch = i4 / (Hh * Ww);
    int r  = i4 - ch * (Hh * Ww);
    int y  = r / Ww;
    int x  = r - y * Ww;                     // multiple of 4
    size_t rb = ((size_t)ch * Hh + y) * BPW;
    *(uint2*)(g_Bp + rb + x + 8) = make_uint2(h2_bits(b01), h2_bits(b23));
    __half* p2 = g_Bp2 + rb + x + 7;
    p2[0] = __low2half(b01);  p2[1] = __high2half(b01);
    p2[2] = __low2half(b23);  p2[3] = __high2half(b23);
}

// ---------------------------------------------------------------------------
// Stage one K-block (n, y0, x0) into smem slot s. All 16B aligned cp.async.
// ---------------------------------------------------------------------------
__device__ __forceinline__ void stage_load(u32 smbase, int s, int blk,
                                           int ih, int tid)
{
    const int n  = blk / (Hh * XCH);
    const int r  = blk - n * (Hh * XCH);
    const int y0 = r >> 1;
    const int x0 = (r & 1) * KCH;
    const u32 st = smbase + (u32)s * (SWORDS * 4);

    // A: 5*16*14 = 1120 16B ops
    #pragma unroll
    for (int q = 0; q < 5; ++q) {
        const int idx = tid + q * 256;
        if (idx < 1120) {
            const int i   = idx / 224;
            const int rem = idx - i * 224;
            const int rr  = rem / 14;
            const int c   = rem - rr * 14;
            const int gy  = y0 - 7 + rr;
            const u32 dst = st + (u32)((i * 16 + rr) * APITCHW + c * 4) * 4u;
            const bool ok = (gy >= 0) && (gy < Hh);
            const __half* src = ok
                ? g_Ah + ((size_t)((n * Kc) + ih * 5 + i) * Hh + gy) * Ww + x0 + c * 8
                : g_Ah;
            CP_ASYNC16(dst, src, ok ? 16u : 0u);
        }
    }
    // B: 2 copies x 10 ch x 16 16B ops = 320 ops
    #pragma unroll
    for (int q = 0; q < 2; ++q) {
        const int id2 = tid + q * 256;
        if (id2 < 320) {
            const int cp = (id2 >> 4) >= Kc ? 1 : 0;
            const int jj = (id2 >> 4) - cp * Kc;
            const int c  = id2 & 15;
            const __half* gsrc = (cp ? g_Bp2 : g_Bp)
                + ((size_t)(n * Kc + jj) * Hh + y0) * BPW + x0 + c * 8;
            const u32 dst = st
                + (u32)((cp ? CB1 : CB0) + jj * BPITCHW + c * 4) * 4u;
            CP_ASYNC16(dst, gsrc, 16u);
        }
    }
}

// ---------------------------------------------------------------------------
// grid = (148, 2 i-halves), 256 threads, 2 CTAs/SM, 3-stage pipeline.
// ---------------------------------------------------------------------------
__global__ void __launch_bounds__(256, 2) corr_kernel()
{
    extern __shared__ u32 sm[];
    const u32 smbase = smem_u32(sm);
    const int tid  = threadIdx.x;
    const int ih   = blockIdx.y;
    const int bx   = blockIdx.x;
    const int w    = tid >> 5;
    const int lane = tid & 31;
    const int g    = lane >> 2;
    const int t    = lane & 3;

    const int lo = (int)(((long long)bx * NBLK) / NCTA);
    const int hi = (int)(((long long)(bx + 1) * NBLK) / NCTA);

    const int wg   = w >> 2;          // m-group: 0 -> tiles 0-2, 1 -> 3-4
    const int wn   = w & 3;           // n-quarter
    const int mcnt = wg == 0 ? 3 : 2;

    int ntv[5];
    #pragma unroll
    for (int u = 0; u < 5; ++u) ntv[u] = wn * 5 + u;

    int aoff[3];
    #pragma unroll
    for (int m = 0; m < 3; ++m)
        aoff[m] = ((wg * 3 + m) * 16 + g) * APITCHW;

    int boff[5];
    #pragma unroll
    for (int u = 0; u < 5; ++u) {
        int n = ntv[u] * 8 + g;
        if (n > 149) n = 149;
        const int dxb = n / Kc, jb = n - dxb * Kc;
        const int s15 = 15 - dxb;                       // 1..15
        boff[u] = (s15 & 1)
            ? CB1 + jb * BPITCHW + ((s15 - 1) >> 1)     // odd  -> shifted copy
            : CB0 + jb * BPITCHW + (s15 >> 1);          // even -> aligned copy
    }

    float d[3][5][4];
    #pragma unroll
    for (int m = 0; m < 3; ++m)
        #pragma unroll
        for (int u = 0; u < 5; ++u)
            #pragma unroll
            for (int e = 0; e < 4; ++e) d[m][u][e] = 0.0f;

    // ---- prologue: stage slots 0 and 1 ----
    stage_load(smbase, 0, lo, ih, tid);
    CP_COMMIT();
    if (lo + 1 < hi) stage_load(smbase, 1, lo + 1, ih, tid);
    CP_COMMIT();

    int cur = 0;
    for (int blk = lo; blk < hi; ++blk) {
        CP_WAIT(1);                   // slot cur landed (per-thread)
        __syncthreads();              // all threads' cur data visible;
                                      // also: everyone done computing blk-1
        // stage blk+2 into slot (cur+2)%3 (last read at iter blk-1)
        if (blk + 2 < hi) {
            int s2 = cur + 2; if (s2 >= NST) s2 -= NST;
            stage_load(smbase, s2, blk + 2, ih, tid);
        }
        CP_COMMIT();                  // unconditional: keeps group counts exact

        const u32* sc = sm + cur * SWORDS;
        #pragma unroll
        for (int ks = 0; ks < 7; ++ks) {
            const int kw = ks * 8;
            u32 bf[5][2];
            #pragma unroll
            for (int u = 0; u < 5; ++u) {
                if (ntv[u] < NNT) {
                    bf[u][0] = sc[boff[u] + kw + t];
                    bf[u][1] = sc[boff[u] + kw + t + 4];
                }
            }
            #pragma unroll
            for (int m = 0; m < 3; ++m) {
                if (m < mcnt) {
                    const u32 a0 = sc[aoff[m] + kw + t];
                    const u32 a1 = sc[aoff[m] + 8 * APITCHW + kw + t];
                    const u32 a2 = sc[aoff[m] + kw + t + 4];
                    const u32 a3 = sc[aoff[m] + 8 * APITCHW + kw + t + 4];
                    #pragma unroll
                    for (int u = 0; u < 5; ++u)
                        if (ntv[u] < NNT)
                            MMA_F16(d[m][u], a0, a1, a2, a3, bf[u][0], bf[u][1]);
                }
            }
        }
        if (++cur == NST) cur = 0;
    }

    // ---- epilogue: atomic fold into g_p ----
    #pragma unroll
    for (int m = 0; m < 3; ++m) {
        if (m >= mcnt) continue;
        const int ig = ih * 5 + wg * 3 + m;
        #pragma unroll
        for (int u = 0; u < 5; ++u) {
            if (ntv[u] >= NNT) continue;
            #pragma unroll
            for (int e = 0; e < 4; ++e) {
                const int dy = g + (e >> 1) * 8;
                const int nn = ntv[u] * 8 + 2 * t + (e & 1);
                if (dy < Tn && nn < Tn * Kc) {
                    const int dx = nn / Kc;
                    const int j  = nn - dx * Kc;
                    atomicAdd(&g_p[((dy * Tn + dx) * Kc + ig) * Kc + j],
                              d[m][u][e]);
                }
            }
        }
    }
}

// ---------------------------------------------------------------------------
// min (parallel, atomicMin on positive-float bits) + per-shift loss.
// ---------------------------------------------------------------------------
__global__ void min_kernel() {
    __shared__ float red[256];
    const int tid = threadIdx.x;
    const int idx = blockIdx.x * 256 + tid;
    float m = (idx < NBINS) ? g_p[idx] : 3.402823466e38f;
    red[tid] = m;
    __syncthreads();
    for (int s = 128; s > 0; s >>= 1) {
        if (tid < s) red[tid] = fminf(red[tid], red[tid + s]);
        __syncthreads();
    }
    if (tid == 0) atomicMin(&g_min_bits, __float_as_uint(red[0]));
}

__global__ void loss_kernel(float* __restrict__ out) {
    __shared__ float sv[100];
    __shared__ float ss[100];
    __shared__ float red[128];
    const int t   = blockIdx.x;          // shift 0..224
    const int tid = threadIdx.x;         // 0..127
    const float m = __uint_as_float(g_min_bits);

    float v = 0.0f;
    if (tid < 100) {
        v = g_p[t * 100 + tid] - m + 1e-16f;
        sv[tid] = v;
    }
    red[tid] = (tid < 100) ? v : 0.0f;
    __syncthreads();
    for (int s = 64; s > 0; s >>= 1) {
        if (tid < s) red[tid] += red[tid + s];
        __syncthreads();
    }
    const float inv = 1.0f / red[0];
    __syncthreads();

    const int i = tid / 10, j = tid - (tid / 10) * 10;
    float sym = 0.0f;
    if (tid < 100) {
        sym = (i == j) ? v * inv : 0.5f * (v + sv[j * 10 + i]) * inv;
        ss[tid] = sym;
    }
    __syncthreads();

    float l = 0.0f;
    if (tid < 100) {
        float pi = 0.0f, pj = 0.0f;
        #pragma unroll
        for (int q = 0; q < 10; ++q) {
            pi += ss[q * 10 + j];
            pj += ss[i * 10 + q];
        }
        l = -sym * (logf(sym + 1e-16f) - logf(pi + 1e-16f) - logf(pj + 1e-16f));
    }
    red[tid] = l;
    __syncthreads();
    for (int s = 64; s > 0; s >>= 1) {
        if (tid < s) red[tid] += red[tid + s];
        __syncthreads();
    }
    if (tid == 0) atomicAdd(out, red[0] * (1.0f / (Tn * Tn)));
}

// ---------------------------------------------------------------------------
extern "C" void kernel_launch(void* const* d_in, const int* in_sizes, int n_in,
                              void* d_out, int out_size)
{
    (void)in_sizes; (void)n_in; (void)out_size;
    const float* A = (const float*)d_in[0];   // x_out    (16,10,224,224) f32
    const float* B = (const float*)d_in[1];   // x_tf_out (16,10,224,224) f32
    float* out = (float*)d_out;

    cudaFuncSetAttribute(corr_kernel,
                         cudaFuncAttributeMaxDynamicSharedMemorySize, SMEM_DYN);

    convert_kernel<<<NELEM / 4 / 256, 256>>>(A, B, out);
    corr_kernel<<<dim3(NCTA, 2), 256, SMEM_DYN>>>();
    min_kernel<<<(NBINS + 255) / 256, 256>>>();
    loss_kernel<<<Tn * Tn, 128>>>(out);
}